// round 12
// baseline (speedup 1.0000x reference)
#include <cuda_runtime.h>
#include <cuda_fp16.h>
#include <cstdint>
#include <cstddef>

// ===========================================================================
// Flash attention via mma.sync.m16n8k16 (fp16-split for fp32 accuracy).
// Q,K,V fp32 [D=128, N=8192] feature-major. out[d,q] fp32.
// R12: ping-pong warp groups — warps 0-3 (q 0-63) and 4-7 (q 64-127) walk the
//      KV stream independently (own rings, BK=32, B rotated by half the kv and
//      staggered ~half a tile), so SMSP partners (w, w+4) anti-phase: one
//      warp's softmax overlaps the other's HMMA burst.
// grid = (64 q-blocks, 2 kv-splits); combine kernel merges partials.
// ===========================================================================

namespace {

constexpr int D_ = 128;
constexpr int N_ = 8192;
constexpr int BQ = 128;
constexpr int BK = 32;
constexpr int SPLIT = 2;
constexpr int KVLEN = N_ / SPLIT;   // 4096
constexpr int NT = KVLEN / BK;      // 128 tiles per group
constexpr int NTHREADS = 256;

constexpr int QSTR = 136;           // halves per Q row (272 B, conflict-free)
constexpr int TSTR = 40;            // halves per K/V tile row (80 B, conflict-free)

// smem byte offsets
constexpr int SMBAR = 0;            // 9 mbarriers x 8 B (full/free per group + stagger)
constexpr int SQHI = 96;
constexpr int SQLO = SQHI + D_ * QSTR * 2;          // +34816
constexpr int SBUF = SQLO + D_ * QSTR * 2;          // 69728
constexpr int SUB  = D_ * TSTR * 2;                 // 10240 per sub-tile
constexpr int KH_OFF = 0, KL_OFF = SUB, VH_OFF = 2 * SUB;
constexpr int BUFB = 3 * SUB;                       // 30720
constexpr int SMEM_BYTES = SBUF + 4 * BUFB;         // 192,608 (1 CTA/SM)

constexpr float LOG2E  = 1.4426950408889634f;
constexpr float THRESH = 11.5f;                     // ~8 nats, in log2 units

// pre-split K (hi/lo) and V (single fp16), written once by cvt_kernel
__device__ __half g_Khi[D_][N_];
__device__ __half g_Klo[D_][N_];
__device__ __half g_Vhi[D_][N_];

// kv-split combine scratch (m in log2 units)
__device__ float g_Op[SPLIT][D_][N_];
__device__ float g_m[SPLIT][N_];
__device__ float g_l[SPLIT][N_];

__device__ __forceinline__ uint32_t smem_u32(const void* p) {
    uint32_t a;
    asm("{ .reg .u64 t; cvta.to.shared.u64 t, %1; cvt.u32.u64 %0, t; }" : "=r"(a) : "l"(p));
    return a;
}
__device__ __forceinline__ void cp16(uint32_t s, const void* g) {
    asm volatile("cp.async.cg.shared.global [%0], [%1], 16;\n" :: "r"(s), "l"(g));
}
__device__ __forceinline__ void mbar_init(uint32_t mb, uint32_t cnt) {
    asm volatile("mbarrier.init.shared.b64 [%0], %1;" :: "r"(mb), "r"(cnt) : "memory");
}
__device__ __forceinline__ void mbar_arrive(uint32_t mb) {
    uint64_t s;
    asm volatile("mbarrier.arrive.shared.b64 %0, [%1];" : "=l"(s) : "r"(mb) : "memory");
}
__device__ __forceinline__ void cpasync_mbar_arrive(uint32_t mb) {
    asm volatile("cp.async.mbarrier.arrive.noinc.shared.b64 [%0];" :: "r"(mb) : "memory");
}
__device__ __forceinline__ void mbar_wait(uint32_t mb, uint32_t par) {
    uint32_t done = 0;
    while (!done) {
        asm volatile("{\n\t.reg .pred p;\n\t"
                     "mbarrier.test_wait.parity.shared.b64 p, [%1], %2;\n\t"
                     "selp.b32 %0, 1, 0, p;\n\t}"
                     : "=r"(done) : "r"(mb), "r"(par) : "memory");
    }
}
__device__ __forceinline__ void ldsm4(uint32_t* r, uint32_t addr) {
    asm volatile("ldmatrix.sync.aligned.m8n8.x4.shared.b16 {%0,%1,%2,%3}, [%4];"
                 : "=r"(r[0]), "=r"(r[1]), "=r"(r[2]), "=r"(r[3]) : "r"(addr));
}
__device__ __forceinline__ void ldsm4t(uint32_t* r, uint32_t addr) {
    asm volatile("ldmatrix.sync.aligned.m8n8.x4.trans.shared.b16 {%0,%1,%2,%3}, [%4];"
                 : "=r"(r[0]), "=r"(r[1]), "=r"(r[2]), "=r"(r[3]) : "r"(addr));
}
__device__ __forceinline__ void mma16816(float* c, const uint32_t* a,
                                         uint32_t b0, uint32_t b1) {
    asm volatile("mma.sync.aligned.m16n8k16.row.col.f32.f16.f16.f32 "
                 "{%0,%1,%2,%3},{%4,%5,%6,%7},{%8,%9},{%0,%1,%2,%3};"
                 : "+f"(c[0]), "+f"(c[1]), "+f"(c[2]), "+f"(c[3])
                 : "r"(a[0]), "r"(a[1]), "r"(a[2]), "r"(a[3]), "r"(b0), "r"(b1));
}
__device__ __forceinline__ uint32_t h2bits(__half2 h) {
    return *reinterpret_cast<uint32_t*>(&h);
}
__device__ __forceinline__ void cvt_sts(float4 v, char* hi, char* lo, uint32_t off) {
    __half2 h01 = __floats2half2_rn(v.x, v.y);
    __half2 h23 = __floats2half2_rn(v.z, v.w);
    float2 f01 = __half22float2(h01);
    float2 f23 = __half22float2(h23);
    __half2 l01 = __floats2half2_rn(v.x - f01.x, v.y - f01.y);
    __half2 l23 = __floats2half2_rn(v.z - f23.x, v.w - f23.y);
    *(uint2*)(hi + off) = make_uint2(h2bits(h01), h2bits(h23));
    *(uint2*)(lo + off) = make_uint2(h2bits(l01), h2bits(l23));
}

// ---------------- precompute: K -> hi/lo fp16, V -> fp16 ----------------
__global__ void __launch_bounds__(256)
cvt_kernel(const float* __restrict__ K, const float* __restrict__ V)
{
    int idx = blockIdx.x * 256 + threadIdx.x;
    int tsel = idx >> 18;
    int rem  = idx & 262143;
    int d    = rem >> 11;
    int c4   = (rem & 2047) << 2;
    const float* src = tsel ? V : K;
    float4 v = *(const float4*)(src + (size_t)d * N_ + c4);
    __half2 h01 = __floats2half2_rn(v.x, v.y);
    __half2 h23 = __floats2half2_rn(v.z, v.w);
    __half* hi = tsel ? g_Vhi[d] : g_Khi[d];
    *(uint2*)(hi + c4) = make_uint2(h2bits(h01), h2bits(h23));
    if (!tsel) {
        float2 f01 = __half22float2(h01);
        float2 f23 = __half22float2(h23);
        __half2 l01 = __floats2half2_rn(v.x - f01.x, v.y - f01.y);
        __half2 l23 = __floats2half2_rn(v.z - f23.x, v.w - f23.y);
        *(uint2*)(g_Klo[d] + c4) = make_uint2(h2bits(l01), h2bits(l23));
    }
}

__global__ void noop_kernel() {}

__global__ void __launch_bounds__(NTHREADS, 1)
attn_mma(const float* __restrict__ Q)
{
    extern __shared__ __align__(1024) char smem[];
    const uint32_t sb = smem_u32(smem);
    const int tid  = threadIdx.x;
    const int lane = tid & 31;
    const int w    = tid >> 5;
    const int g    = w >> 2;           // warp group: 0 (q 0-63) / 1 (q 64-127)
    const int gt   = tid & 127;        // thread id within group
    const int qBase = blockIdx.x * BQ;
    const int kBase = blockIdx.y * KVLEN;
    const int sp    = blockIdx.y;

    // mbarriers: [g][full0, full1, free0, free1] + stagger
    const uint32_t mb_full0 = sb + SMBAR + g * 32;
    const uint32_t mb_full1 = mb_full0 + 8;
    const uint32_t mb_free0 = mb_full0 + 16;
    const uint32_t mb_free1 = mb_full0 + 24;
    const uint32_t mb_stag  = sb + SMBAR + 64;

    if (tid == 0) {
        #pragma unroll
        for (int i = 0; i < 8; ++i) mbar_init(sb + SMBAR + i * 8, 128);
        mbar_init(mb_stag, 128);
    }
    __syncthreads();

    // per-thread cp.async geometry (tile array = 128d x 32k halves)
    int cpd[4], cpk[4];
    uint32_t cpo[4];
    #pragma unroll
    for (int it = 0; it < 4; ++it) {
        int f = gt + it * 128;                 // 0..511
        cpd[it] = f >> 2;
        cpk[it] = (f & 3) << 3;
        cpo[it] = (uint32_t)(cpd[it] * TSTR + cpk[it]) * 2;
    }

    auto issue_tile = [&](int k0, uint32_t dst) {
        #pragma unroll
        for (int it = 0; it < 4; ++it) {
            const int d = cpd[it], kg = k0 + cpk[it];
            cp16(dst + KH_OFF + cpo[it], g_Khi[d] + kg);
            cp16(dst + KL_OFF + cpo[it], g_Klo[d] + kg);
            cp16(dst + VH_OFF + cpo[it], g_Vhi[d] + kg);
        }
    };
    auto buf_base = [&](int b) -> uint32_t {
        return sb + SBUF + (uint32_t)(g * 2 + b) * BUFB;
    };
    auto tile_k0 = [&](int i) -> int {
        return kBase + (((i + (g << 6)) & (NT - 1)) * BK);
    };

    // ---- load Q [d][q] hi/lo into smem, pre-scaled by log2(e) ----
    #pragma unroll
    for (int it = 0; it < 16; ++it) {
        int f = tid + it * NTHREADS;       // 4096 float4s (128d x 128q)
        int d = f >> 5;
        int qc = (f & 31) << 2;
        float4 v = *(const float4*)(Q + (size_t)d * N_ + qBase + qc);
        v.x *= LOG2E; v.y *= LOG2E; v.z *= LOG2E; v.w *= LOG2E;
        cvt_sts(v, smem + SQHI, smem + SQLO, (uint32_t)(d * QSTR + qc) * 2);
    }

    // ---- prologue: each group loads its first tile into its buffer 0 ----
    issue_tile(tile_k0(0), buf_base(0));
    cpasync_mbar_arrive(mb_full0);
    __syncthreads();       // Q tile visible to all warps

    // per-lane ldmatrix offsets
    const int q0 = w * 16;
    const uint32_t qa_off = sb + SQHI +
        (uint32_t)(((((lane >> 4) << 3) + (lane & 7)) * QSTR +
                    q0 + (((lane >> 3) & 1) << 3)) * 2);
    const uint32_t kb_off =
        (uint32_t)(((((lane >> 3) & 1) << 3) + (lane & 7)) * TSTR +
                   (((lane >> 4) << 3))) * 2;
    const uint32_t vb_off =
        (uint32_t)((((lane >> 4) << 3) + (lane & 7)) * TSTR +
                   ((((lane >> 3) & 1) << 3))) * 2;

    float oacc[16][4];
    #pragma unroll
    for (int i = 0; i < 16; ++i)
        #pragma unroll
        for (int j = 0; j < 4; ++j) oacc[i][j] = 0.0f;
    float m0 = -1e30f, m1 = -1e30f, l0 = 0.0f, l1 = 0.0f;

    // ---- stagger: group B waits until group A has finished S(0) issue ----
    if (g == 1) mbar_wait(mb_stag, 0);

    for (int t = 0; t < NT; ++t) {
        const int cur = t & 1;
        const uint32_t bufK = buf_base(cur);
        const uint32_t bufV = bufK + VH_OFF;
        const uint32_t mb_full_cur = cur ? mb_full1 : mb_full0;
        const uint32_t mb_free_cur = cur ? mb_free1 : mb_free0;

        // ---- produce tile t+1 into the other buffer ----
        if (t + 1 < NT) {
            const int nb = cur ^ 1;
            const int m = (t + 1) >> 1;          // reuse index of buffer nb
            if (m >= 1) mbar_wait(nb ? mb_free1 : mb_free0, (m - 1) & 1);
            issue_tile(tile_k0(t + 1), buf_base(nb));
            cpasync_mbar_arrive(nb ? mb_full1 : mb_full0);
        }

        // ---- consume tile t ----
        mbar_wait(mb_full_cur, (t >> 1) & 1);

        // ---- S = Q^T K (3 split passes; 4-acc round-robin; 32 keys) ----
        float acc[4][4];
        #pragma unroll
        for (int i = 0; i < 4; ++i)
            #pragma unroll
            for (int j = 0; j < 4; ++j) acc[i][j] = 0.0f;

        #pragma unroll
        for (int s = 0; s < 8; ++s) {          // d-steps of 16
            uint32_t ah[4], al[4];
            ldsm4t(ah, qa_off + s * (16 * QSTR * 2));
            ldsm4t(al, qa_off + (SQLO - SQHI) + s * (16 * QSTR * 2));
            uint32_t bh0[4], bl0[4], bh1[4], bl1[4];
            uint32_t ka = bufK + kb_off + s * (16 * TSTR * 2);
            ldsm4t(bh0, ka + KH_OFF);
            ldsm4t(bl0, ka + KL_OFF);
            ldsm4t(bh1, ka + KH_OFF + 32);
            ldsm4t(bl1, ka + KL_OFF + 32);
            mma16816(acc[0], ah, bh0[0], bh0[1]);
            mma16816(acc[1], ah, bh0[2], bh0[3]);
            mma16816(acc[2], ah, bh1[0], bh1[1]);
            mma16816(acc[3], ah, bh1[2], bh1[3]);
            mma16816(acc[0], ah, bl0[0], bl0[1]);
            mma16816(acc[1], ah, bl0[2], bl0[3]);
            mma16816(acc[2], ah, bl1[0], bl1[1]);
            mma16816(acc[3], ah, bl1[2], bl1[3]);
            mma16816(acc[0], al, bh0[0], bh0[1]);
            mma16816(acc[1], al, bh0[2], bh0[3]);
            mma16816(acc[2], al, bh1[0], bh1[1]);
            mma16816(acc[3], al, bh1[2], bh1[3]);
        }

        // group A releases group B after S(0) is issued (half-tile offset)
        if (g == 0 && t == 0) mbar_arrive(mb_stag);

        // ---- online softmax (log2 domain): max + rescale ----
        float tm0 = -1e30f, tm1 = -1e30f;
        #pragma unroll
        for (int nt = 0; nt < 4; ++nt) {
            tm0 = fmaxf(tm0, fmaxf(acc[nt][0], acc[nt][1]));
            tm1 = fmaxf(tm1, fmaxf(acc[nt][2], acc[nt][3]));
        }
        tm0 = fmaxf(tm0, __shfl_xor_sync(0xffffffffu, tm0, 1));
        tm0 = fmaxf(tm0, __shfl_xor_sync(0xffffffffu, tm0, 2));
        tm1 = fmaxf(tm1, __shfl_xor_sync(0xffffffffu, tm1, 1));
        tm1 = fmaxf(tm1, __shfl_xor_sync(0xffffffffu, tm1, 2));

        bool upd = (tm0 > m0 + THRESH) || (tm1 > m1 + THRESH);
        if (__ballot_sync(0xffffffffu, upd)) {
            float nm0 = fmaxf(m0, tm0), nm1 = fmaxf(m1, tm1);
            float a0 = exp2f(m0 - nm0), a1 = exp2f(m1 - nm1);
            m0 = nm0; m1 = nm1; l0 *= a0; l1 *= a1;
            #pragma unroll
            for (int nt = 0; nt < 16; ++nt) {
                oacc[nt][0] *= a0; oacc[nt][1] *= a0;
                oacc[nt][2] *= a1; oacc[nt][3] *= a1;
            }
        }

        // ---- exp2/pack interleaved with PV MMA chunks (P fp16, V fp16) ----
        #pragma unroll
        for (int s = 0; s < 2; ++s) {          // k-steps of 16
            uint32_t ah[4];
            #pragma unroll
            for (int half = 0; half < 2; ++half) {
                float* av = acc[2 * s + half];
                float p0 = exp2f(av[0] - m0);
                float p1 = exp2f(av[1] - m0);
                float p2 = exp2f(av[2] - m1);
                float p3 = exp2f(av[3] - m1);
                l0 += p0 + p1; l1 += p2 + p3;
                ah[2 * half]     = h2bits(__floats2half2_rn(p0, p1));
                ah[2 * half + 1] = h2bits(__floats2half2_rn(p2, p3));
            }
            #pragma unroll
            for (int np = 0; np < 8; ++np) {   // d-tile pairs (16 dims)
                uint32_t bh[4];
                uint32_t va = bufV + vb_off + np * (16 * TSTR * 2) + s * 32;
                ldsm4(bh, va);
                mma16816(oacc[2 * np],     ah, bh[0], bh[1]);
                mma16816(oacc[2 * np + 1], ah, bh[2], bh[3]);
            }
        }

        mbar_arrive(mb_free_cur);   // done reading buffer cur
    }

    // ---- epilogue ----
    l0 += __shfl_xor_sync(0xffffffffu, l0, 1);
    l0 += __shfl_xor_sync(0xffffffffu, l0, 2);
    l1 += __shfl_xor_sync(0xffffffffu, l1, 1);
    l1 += __shfl_xor_sync(0xffffffffu, l1, 2);

    const int qr0 = qBase + q0 + (lane >> 2);
    const int qr1 = qr0 + 8;
    if ((lane & 3) == 0) {
        g_m[sp][qr0] = m0; g_m[sp][qr1] = m1;
        g_l[sp][qr0] = l0; g_l[sp][qr1] = l1;
    }
    #pragma unroll
    for (int nt = 0; nt < 16; ++nt) {
        int d = nt * 8 + ((lane & 3) << 1);
        g_Op[sp][d][qr0]     = oacc[nt][0];
        g_Op[sp][d + 1][qr0] = oacc[nt][1];
        g_Op[sp][d][qr1]     = oacc[nt][2];
        g_Op[sp][d + 1][qr1] = oacc[nt][3];
    }
}

__global__ void __launch_bounds__(256)
combine_kernel(float* __restrict__ O)
{
    int idx = blockIdx.x * 256 + threadIdx.x;    // 262144 float4s
    int d  = idx >> 11;
    int q4 = (idx & 2047) << 2;
    float4 o1 = *(const float4*)&g_Op[0][d][q4];
    float4 o2 = *(const float4*)&g_Op[1][d][q4];
    float r[4];
    const float* po1 = &o1.x;
    const float* po2 = &o2.x;
    #pragma unroll
    for (int c = 0; c < 4; ++c) {
        float m1 = g_m[0][q4 + c], m2 = g_m[1][q4 + c];
        float l1 = g_l[0][q4 + c], l2 = g_l[1][q4 + c];
        float M  = fmaxf(m1, m2);
        float w1 = exp2f(m1 - M), w2 = exp2f(m2 - M);
        r[c] = (w1 * po1[c] + w2 * po2[c]) / (w1 * l1 + w2 * l2);
    }
    *(float4*)(O + (size_t)d * N_ + q4) = make_float4(r[0], r[1], r[2], r[3]);
}

} // namespace

extern "C" void kernel_launch(void* const* d_in, const int* in_sizes, int n_in,
                              void* d_out, int out_size) {
    const float* Q = (const float*)d_in[0];
    const float* K = (const float*)d_in[1];
    const float* V = (const float*)d_in[2];
    float* O = (float*)d_out;

    cudaFuncSetAttribute(attn_mma, cudaFuncAttributeMaxDynamicSharedMemorySize,
                         SMEM_BYTES);
    cvt_kernel<<<2048, 256>>>(K, V);          // idx 0
    noop_kernel<<<1, 32>>>();                  // idx 1
    noop_kernel<<<1, 32>>>();                  // idx 2
    dim3 grid(N_ / BQ, SPLIT);
    attn_mma<<<grid, NTHREADS, SMEM_BYTES>>>(Q);   // idx 3 <- ncu
    combine_kernel<<<(D_ * N_ / 4) / 256, 256>>>(O);
}

// round 13
// speedup vs baseline: 1.2941x; 1.2941x over previous
#include <cuda_runtime.h>
#include <cuda_fp16.h>
#include <cstdint>
#include <cstddef>

// ===========================================================================
// Flash attention via mma.sync.m16n8k16 (fp16-split for fp32 accuracy).
// Q,K,V fp32 [D=128, N=8192] feature-major. out[d,q] fp32.
// R13: R10 base (BK=64, chunked softmax+PV) with d-outer S-phase — Q hi/lo
//      fragments loaded once per d-step, reused across both key chunks
//      (cuts Q ldsm in half; smem crossbar is a binding floor).
// grid = (64 q-blocks, 2 kv-splits); combine kernel merges partials.
// ===========================================================================

namespace {

constexpr int D_ = 128;
constexpr int N_ = 8192;
constexpr int BQ = 128;
constexpr int BK = 64;
constexpr int SPLIT = 2;
constexpr int KVLEN = N_ / SPLIT;   // 4096
constexpr int NT = KVLEN / BK;      // 64 tiles
constexpr int NTHREADS = 256;

constexpr int QSTR = 136;           // halves per Q row (272 B, conflict-free)
constexpr int TSTR = 72;            // halves per K/V tile row (144 B)

// smem byte offsets
constexpr int SMBAR = 0;                            // 4 mbarriers x 8 B
constexpr int SQHI = 32;
constexpr int SQLO = SQHI + D_ * QSTR * 2;
constexpr int SBUF = SQLO + D_ * QSTR * 2;
constexpr int SUB  = D_ * TSTR * 2;                 // 18432 per sub-tile
constexpr int KH_OFF = 0, KL_OFF = SUB, VH_OFF = 2 * SUB;
constexpr int BUFB = 3 * SUB;                       // 55296
constexpr int SMEM_BYTES = SBUF + 2 * BUFB;         // 180,256

constexpr float LOG2E  = 1.4426950408889634f;
constexpr float THRESH = 11.5f;                     // ~8 nats, in log2 units

// pre-split K (hi/lo) and V (single fp16), written once by cvt_kernel
__device__ __half g_Khi[D_][N_];
__device__ __half g_Klo[D_][N_];
__device__ __half g_Vhi[D_][N_];

// kv-split combine scratch (m in log2 units)
__device__ float g_Op[SPLIT][D_][N_];
__device__ float g_m[SPLIT][N_];
__device__ float g_l[SPLIT][N_];

__device__ __forceinline__ uint32_t smem_u32(const void* p) {
    uint32_t a;
    asm("{ .reg .u64 t; cvta.to.shared.u64 t, %1; cvt.u32.u64 %0, t; }" : "=r"(a) : "l"(p));
    return a;
}
__device__ __forceinline__ void cp16(uint32_t s, const void* g) {
    asm volatile("cp.async.cg.shared.global [%0], [%1], 16;\n" :: "r"(s), "l"(g));
}
__device__ __forceinline__ void mbar_init(uint32_t mb, uint32_t cnt) {
    asm volatile("mbarrier.init.shared.b64 [%0], %1;" :: "r"(mb), "r"(cnt) : "memory");
}
__device__ __forceinline__ void mbar_arrive(uint32_t mb) {
    uint64_t s;
    asm volatile("mbarrier.arrive.shared.b64 %0, [%1];" : "=l"(s) : "r"(mb) : "memory");
}
__device__ __forceinline__ void cpasync_mbar_arrive(uint32_t mb) {
    asm volatile("cp.async.mbarrier.arrive.noinc.shared.b64 [%0];" :: "r"(mb) : "memory");
}
__device__ __forceinline__ void mbar_wait(uint32_t mb, uint32_t par) {
    uint32_t done = 0;
    while (!done) {
        asm volatile("{\n\t.reg .pred p;\n\t"
                     "mbarrier.test_wait.parity.shared.b64 p, [%1], %2;\n\t"
                     "selp.b32 %0, 1, 0, p;\n\t}"
                     : "=r"(done) : "r"(mb), "r"(par) : "memory");
    }
}
__device__ __forceinline__ void ldsm4(uint32_t* r, uint32_t addr) {
    asm volatile("ldmatrix.sync.aligned.m8n8.x4.shared.b16 {%0,%1,%2,%3}, [%4];"
                 : "=r"(r[0]), "=r"(r[1]), "=r"(r[2]), "=r"(r[3]) : "r"(addr));
}
__device__ __forceinline__ void ldsm4t(uint32_t* r, uint32_t addr) {
    asm volatile("ldmatrix.sync.aligned.m8n8.x4.trans.shared.b16 {%0,%1,%2,%3}, [%4];"
                 : "=r"(r[0]), "=r"(r[1]), "=r"(r[2]), "=r"(r[3]) : "r"(addr));
}
__device__ __forceinline__ void mma16816(float* c, const uint32_t* a,
                                         uint32_t b0, uint32_t b1) {
    asm volatile("mma.sync.aligned.m16n8k16.row.col.f32.f16.f16.f32 "
                 "{%0,%1,%2,%3},{%4,%5,%6,%7},{%8,%9},{%0,%1,%2,%3};"
                 : "+f"(c[0]), "+f"(c[1]), "+f"(c[2]), "+f"(c[3])
                 : "r"(a[0]), "r"(a[1]), "r"(a[2]), "r"(a[3]), "r"(b0), "r"(b1));
}
__device__ __forceinline__ uint32_t h2bits(__half2 h) {
    return *reinterpret_cast<uint32_t*>(&h);
}
__device__ __forceinline__ void cvt_sts(float4 v, char* hi, char* lo, uint32_t off) {
    __half2 h01 = __floats2half2_rn(v.x, v.y);
    __half2 h23 = __floats2half2_rn(v.z, v.w);
    float2 f01 = __half22float2(h01);
    float2 f23 = __half22float2(h23);
    __half2 l01 = __floats2half2_rn(v.x - f01.x, v.y - f01.y);
    __half2 l23 = __floats2half2_rn(v.z - f23.x, v.w - f23.y);
    *(uint2*)(hi + off) = make_uint2(h2bits(h01), h2bits(h23));
    *(uint2*)(lo + off) = make_uint2(h2bits(l01), h2bits(l23));
}

// ---------------- precompute: K -> hi/lo fp16, V -> fp16 ----------------
__global__ void __launch_bounds__(256)
cvt_kernel(const float* __restrict__ K, const float* __restrict__ V)
{
    int idx = blockIdx.x * 256 + threadIdx.x;
    int tsel = idx >> 18;
    int rem  = idx & 262143;
    int d    = rem >> 11;
    int c4   = (rem & 2047) << 2;
    const float* src = tsel ? V : K;
    float4 v = *(const float4*)(src + (size_t)d * N_ + c4);
    __half2 h01 = __floats2half2_rn(v.x, v.y);
    __half2 h23 = __floats2half2_rn(v.z, v.w);
    __half* hi = tsel ? g_Vhi[d] : g_Khi[d];
    *(uint2*)(hi + c4) = make_uint2(h2bits(h01), h2bits(h23));
    if (!tsel) {
        float2 f01 = __half22float2(h01);
        float2 f23 = __half22float2(h23);
        __half2 l01 = __floats2half2_rn(v.x - f01.x, v.y - f01.y);
        __half2 l23 = __floats2half2_rn(v.z - f23.x, v.w - f23.y);
        *(uint2*)(g_Klo[d] + c4) = make_uint2(h2bits(l01), h2bits(l23));
    }
}

__global__ void noop_kernel() {}

__global__ void __launch_bounds__(NTHREADS, 1)
attn_mma(const float* __restrict__ Q)
{
    extern __shared__ __align__(1024) char smem[];
    const uint32_t sb = smem_u32(smem);
    const int tid  = threadIdx.x;
    const int lane = tid & 31;
    const int w    = tid >> 5;
    const int qBase = blockIdx.x * BQ;
    const int kBase = blockIdx.y * KVLEN;
    const int sp    = blockIdx.y;

    const uint32_t mb_full[2] = { sb + SMBAR,      sb + SMBAR + 8 };
    const uint32_t mb_free[2] = { sb + SMBAR + 16, sb + SMBAR + 24 };

    if (tid == 0) {
        mbar_init(mb_full[0], NTHREADS);
        mbar_init(mb_full[1], NTHREADS);
        mbar_init(mb_free[0], NTHREADS);
        mbar_init(mb_free[1], NTHREADS);
    }
    __syncthreads();

    // per-thread cp.async geometry
    int cpd[4], cpk[4];
    uint32_t cpo[4];
    #pragma unroll
    for (int it = 0; it < 4; ++it) {
        int f = tid + it * NTHREADS;           // 0..1023
        cpd[it] = f >> 3;
        cpk[it] = (f & 7) << 3;
        cpo[it] = (uint32_t)(cpd[it] * TSTR + cpk[it]) * 2;
    }

    auto issue_tile = [&](int k0, uint32_t dst) {
        #pragma unroll
        for (int it = 0; it < 4; ++it) {
            const int d = cpd[it], kg = k0 + cpk[it];
            cp16(dst + KH_OFF + cpo[it], g_Khi[d] + kg);
            cp16(dst + KL_OFF + cpo[it], g_Klo[d] + kg);
            cp16(dst + VH_OFF + cpo[it], g_Vhi[d] + kg);
        }
    };

    // ---- load Q [d][q] hi/lo into smem, pre-scaled by log2(e) ----
    #pragma unroll
    for (int it = 0; it < 16; ++it) {
        int f = tid + it * NTHREADS;       // 4096 float4s
        int d = f >> 5;
        int qc = (f & 31) << 2;
        float4 v = *(const float4*)(Q + (size_t)d * N_ + qBase + qc);
        v.x *= LOG2E; v.y *= LOG2E; v.z *= LOG2E; v.w *= LOG2E;
        cvt_sts(v, smem + SQHI, smem + SQLO, (uint32_t)(d * QSTR + qc) * 2);
    }

    // ---- prologue: tile 0 into buffer 0 ----
    issue_tile(kBase, sb + SBUF);
    cpasync_mbar_arrive(mb_full[0]);
    __syncthreads();       // Q tile visible to all warps

    // per-lane ldmatrix offsets
    const int q0 = w * 16;
    const uint32_t qa_off = sb + SQHI +
        (uint32_t)(((((lane >> 4) << 3) + (lane & 7)) * QSTR +
                    q0 + (((lane >> 3) & 1) << 3)) * 2);
    const uint32_t kb_off =
        (uint32_t)(((((lane >> 3) & 1) << 3) + (lane & 7)) * TSTR +
                   (((lane >> 4) << 3))) * 2;
    const uint32_t vb_off =
        (uint32_t)((((lane >> 4) << 3) + (lane & 7)) * TSTR +
                   ((((lane >> 3) & 1) << 3))) * 2;

    float oacc[16][4];
    #pragma unroll
    for (int i = 0; i < 16; ++i)
        #pragma unroll
        for (int j = 0; j < 4; ++j) oacc[i][j] = 0.0f;
    float m0 = -1e30f, m1 = -1e30f, l0 = 0.0f, l1 = 0.0f;

    for (int t = 0; t < NT; ++t) {
        const int cur = t & 1;
        const uint32_t bufK = sb + SBUF + cur * BUFB;
        const uint32_t bufV = bufK + VH_OFF;
        const uint32_t mb_full_cur = mb_full[cur];
        const uint32_t mb_free_cur = mb_free[cur];

        // ---- produce tile t+1 into the other buffer ----
        if (t + 1 < NT) {
            const int nb = cur ^ 1;
            const int m = (t + 1) >> 1;          // reuse index of buffer nb
            if (m >= 1) mbar_wait(mb_free[nb], (m - 1) & 1);
            issue_tile(kBase + (t + 1) * BK, sb + SBUF + nb * BUFB);
            cpasync_mbar_arrive(mb_full[nb]);
        }

        // ---- consume tile t ----
        mbar_wait(mb_full_cur, (t >> 1) & 1);

        // ---- S = Q^T K: d-outer, Q frags shared across both key chunks ----
        float acc[8][4];
        #pragma unroll
        for (int i = 0; i < 8; ++i)
            #pragma unroll
            for (int j = 0; j < 4; ++j) acc[i][j] = 0.0f;

        #pragma unroll
        for (int s = 0; s < 8; ++s) {          // d-steps of 16
            uint32_t ah[4], al[4];
            ldsm4t(ah, qa_off + s * (16 * QSTR * 2));
            ldsm4t(al, qa_off + (SQLO - SQHI) + s * (16 * QSTR * 2));
            #pragma unroll
            for (int c = 0; c < 2; ++c) {      // key chunks of 32
                uint32_t bh0[4], bl0[4], bh1[4], bl1[4];
                uint32_t ka = bufK + kb_off + s * (16 * TSTR * 2) + c * 64;
                ldsm4t(bh0, ka + KH_OFF);
                ldsm4t(bl0, ka + KL_OFF);
                ldsm4t(bh1, ka + KH_OFF + 32);
                ldsm4t(bl1, ka + KL_OFF + 32);
                float* a0 = acc[4 * c];
                float* a1 = acc[4 * c + 1];
                float* a2 = acc[4 * c + 2];
                float* a3 = acc[4 * c + 3];
                mma16816(a0, ah, bh0[0], bh0[1]);
                mma16816(a1, ah, bh0[2], bh0[3]);
                mma16816(a2, ah, bh1[0], bh1[1]);
                mma16816(a3, ah, bh1[2], bh1[3]);
                mma16816(a0, ah, bl0[0], bl0[1]);
                mma16816(a1, ah, bl0[2], bl0[3]);
                mma16816(a2, ah, bl1[0], bl1[1]);
                mma16816(a3, ah, bl1[2], bl1[3]);
                mma16816(a0, al, bh0[0], bh0[1]);
                mma16816(a1, al, bh0[2], bh0[3]);
                mma16816(a2, al, bh1[0], bh1[1]);
                mma16816(a3, al, bh1[2], bh1[3]);
            }
        }

        // ---- per-chunk: softmax + PV, interleaved with tensor bursts ----
        #pragma unroll
        for (int c = 0; c < 2; ++c) {
            float (*ca)[4] = &acc[4 * c];

            float tm0 = -1e30f, tm1 = -1e30f;
            #pragma unroll
            for (int nt = 0; nt < 4; ++nt) {
                tm0 = fmaxf(tm0, fmaxf(ca[nt][0], ca[nt][1]));
                tm1 = fmaxf(tm1, fmaxf(ca[nt][2], ca[nt][3]));
            }
            tm0 = fmaxf(tm0, __shfl_xor_sync(0xffffffffu, tm0, 1));
            tm0 = fmaxf(tm0, __shfl_xor_sync(0xffffffffu, tm0, 2));
            tm1 = fmaxf(tm1, __shfl_xor_sync(0xffffffffu, tm1, 1));
            tm1 = fmaxf(tm1, __shfl_xor_sync(0xffffffffu, tm1, 2));

            bool upd = (tm0 > m0 + THRESH) || (tm1 > m1 + THRESH);
            if (__ballot_sync(0xffffffffu, upd)) {
                float nm0 = fmaxf(m0, tm0), nm1 = fmaxf(m1, tm1);
                float a0 = exp2f(m0 - nm0), a1 = exp2f(m1 - nm1);
                m0 = nm0; m1 = nm1; l0 *= a0; l1 *= a1;
                #pragma unroll
                for (int nt = 0; nt < 16; ++nt) {
                    oacc[nt][0] *= a0; oacc[nt][1] *= a0;
                    oacc[nt][2] *= a1; oacc[nt][3] *= a1;
                }
            }

            // PV over this chunk's two 16-key steps
            #pragma unroll
            for (int sh = 0; sh < 2; ++sh) {
                const int s = 2 * c + sh;      // global k-step
                uint32_t ah[4];
                #pragma unroll
                for (int half = 0; half < 2; ++half) {
                    float* av = ca[2 * sh + half];
                    float p0 = exp2f(av[0] - m0);
                    float p1 = exp2f(av[1] - m0);
                    float p2 = exp2f(av[2] - m1);
                    float p3 = exp2f(av[3] - m1);
                    l0 += p0 + p1; l1 += p2 + p3;
                    ah[2 * half]     = h2bits(__floats2half2_rn(p0, p1));
                    ah[2 * half + 1] = h2bits(__floats2half2_rn(p2, p3));
                }
                #pragma unroll
                for (int np = 0; np < 8; ++np) {   // d-tile pairs (16 dims)
                    uint32_t bh[4];
                    uint32_t va = bufV + vb_off + np * (16 * TSTR * 2) + s * 32;
                    ldsm4(bh, va);
                    mma16816(oacc[2 * np],     ah, bh[0], bh[1]);
                    mma16816(oacc[2 * np + 1], ah, bh[2], bh[3]);
                }
            }
        }

        mbar_arrive(mb_free_cur);   // done reading buffer cur
    }

    // ---- epilogue ----
    l0 += __shfl_xor_sync(0xffffffffu, l0, 1);
    l0 += __shfl_xor_sync(0xffffffffu, l0, 2);
    l1 += __shfl_xor_sync(0xffffffffu, l1, 1);
    l1 += __shfl_xor_sync(0xffffffffu, l1, 2);

    const int qr0 = qBase + q0 + (lane >> 2);
    const int qr1 = qr0 + 8;
    if ((lane & 3) == 0) {
        g_m[sp][qr0] = m0; g_m[sp][qr1] = m1;
        g_l[sp][qr0] = l0; g_l[sp][qr1] = l1;
    }
    #pragma unroll
    for (int nt = 0; nt < 16; ++nt) {
        int d = nt * 8 + ((lane & 3) << 1);
        g_Op[sp][d][qr0]     = oacc[nt][0];
        g_Op[sp][d + 1][qr0] = oacc[nt][1];
        g_Op[sp][d][qr1]     = oacc[nt][2];
        g_Op[sp][d + 1][qr1] = oacc[nt][3];
    }
}

__global__ void __launch_bounds__(256)
combine_kernel(float* __restrict__ O)
{
    int idx = blockIdx.x * 256 + threadIdx.x;    // 262144 float4s
    int d  = idx >> 11;
    int q4 = (idx & 2047) << 2;
    float4 o1 = *(const float4*)&g_Op[0][d][q4];
    float4 o2 = *(const float4*)&g_Op[1][d][q4];
    float r[4];
    const float* po1 = &o1.x;
    const float* po2 = &o2.x;
    #pragma unroll
    for (int c = 0; c < 4; ++c) {
        float m1 = g_m[0][q4 + c], m2 = g_m[1][q4 + c];
        float l1 = g_l[0][q4 + c], l2 = g_l[1][q4 + c];
        float M  = fmaxf(m1, m2);
        float w1 = exp2f(m1 - M), w2 = exp2f(m2 - M);
        r[c] = (w1 * po1[c] + w2 * po2[c]) / (w1 * l1 + w2 * l2);
    }
    *(float4*)(O + (size_t)d * N_ + q4) = make_float4(r[0], r[1], r[2], r[3]);
}

} // namespace

extern "C" void kernel_launch(void* const* d_in, const int* in_sizes, int n_in,
                              void* d_out, int out_size) {
    const float* Q = (const float*)d_in[0];
    const float* K = (const float*)d_in[1];
    const float* V = (const float*)d_in[2];
    float* O = (float*)d_out;

    cudaFuncSetAttribute(attn_mma, cudaFuncAttributeMaxDynamicSharedMemorySize,
                         SMEM_BYTES);
    cvt_kernel<<<2048, 256>>>(K, V);          // idx 0
    noop_kernel<<<1, 32>>>();                  // idx 1
    noop_kernel<<<1, 32>>>();                  // idx 2
    dim3 grid(N_ / BQ, SPLIT);
    attn_mma<<<grid, NTHREADS, SMEM_BYTES>>>(Q);   // idx 3 <- ncu
    combine_kernel<<<(D_ * N_ / 4) / 256, 256>>>(O);
}

// round 14
// speedup vs baseline: 1.3171x; 1.0178x over previous
#include <cuda_runtime.h>
#include <cuda_fp16.h>
#include <cstdint>
#include <cstddef>

// ===========================================================================
// Flash attention via mma.sync.m16n8k16 (fp16-split for fp32 accuracy).
// Q,K,V fp32 [D=128, N=8192] feature-major. out[d,q] fp32.
// R14: 3-buffer KV ring + Qhi fragments in registers; warp-groups (0-3 / 4-7)
//      staggered ~half a tile so SMSP partners anti-phase softmax vs MMA.
// grid = (64 q-blocks, 2 kv-splits); combine kernel merges partials.
// ===========================================================================

namespace {

constexpr int D_ = 128;
constexpr int N_ = 8192;
constexpr int BQ = 128;
constexpr int BK = 64;
constexpr int SPLIT = 2;
constexpr int KVLEN = N_ / SPLIT;   // 4096
constexpr int NT = KVLEN / BK;      // 64 tiles
constexpr int NTHREADS = 256;

constexpr int QSTR = 136;           // halves per Q row (272 B, conflict-free)
constexpr int TSTR = 72;            // halves per K/V tile row (144 B)

// smem byte offsets
constexpr int SMBAR = 0;            // 7 mbarriers x 8 B (full x3, free x3, stag)
constexpr int SQLO  = 128;
constexpr int SBUF  = SQLO + D_ * QSTR * 2;         // 128+34816 = 34944
constexpr int SUB   = D_ * TSTR * 2;                // 18432 per sub-tile
constexpr int KH_OFF = 0, KL_OFF = SUB, VH_OFF = 2 * SUB;
constexpr int BUFB = 3 * SUB;                       // 55296
constexpr int NBUF = 3;
constexpr int SMEM_BYTES = SBUF + NBUF * BUFB;      // 200,832

constexpr float LOG2E  = 1.4426950408889634f;
constexpr float THRESH = 11.5f;                     // ~8 nats, in log2 units

// pre-split K (hi/lo) and V (single fp16), written once by cvt_kernel
__device__ __half g_Khi[D_][N_];
__device__ __half g_Klo[D_][N_];
__device__ __half g_Vhi[D_][N_];

// kv-split combine scratch (m in log2 units)
__device__ float g_Op[SPLIT][D_][N_];
__device__ float g_m[SPLIT][N_];
__device__ float g_l[SPLIT][N_];

__device__ __forceinline__ uint32_t smem_u32(const void* p) {
    uint32_t a;
    asm("{ .reg .u64 t; cvta.to.shared.u64 t, %1; cvt.u32.u64 %0, t; }" : "=r"(a) : "l"(p));
    return a;
}
__device__ __forceinline__ void cp16(uint32_t s, const void* g) {
    asm volatile("cp.async.cg.shared.global [%0], [%1], 16;\n" :: "r"(s), "l"(g));
}
__device__ __forceinline__ void mbar_init(uint32_t mb, uint32_t cnt) {
    asm volatile("mbarrier.init.shared.b64 [%0], %1;" :: "r"(mb), "r"(cnt) : "memory");
}
__device__ __forceinline__ void mbar_arrive(uint32_t mb) {
    uint64_t s;
    asm volatile("mbarrier.arrive.shared.b64 %0, [%1];" : "=l"(s) : "r"(mb) : "memory");
}
__device__ __forceinline__ void cpasync_mbar_arrive(uint32_t mb) {
    asm volatile("cp.async.mbarrier.arrive.noinc.shared.b64 [%0];" :: "r"(mb) : "memory");
}
__device__ __forceinline__ void mbar_wait(uint32_t mb, uint32_t par) {
    uint32_t done = 0;
    while (!done) {
        asm volatile("{\n\t.reg .pred p;\n\t"
                     "mbarrier.test_wait.parity.shared.b64 p, [%1], %2;\n\t"
                     "selp.b32 %0, 1, 0, p;\n\t}"
                     : "=r"(done) : "r"(mb), "r"(par) : "memory");
    }
}
__device__ __forceinline__ void ldsm4(uint32_t* r, uint32_t addr) {
    asm volatile("ldmatrix.sync.aligned.m8n8.x4.shared.b16 {%0,%1,%2,%3}, [%4];"
                 : "=r"(r[0]), "=r"(r[1]), "=r"(r[2]), "=r"(r[3]) : "r"(addr));
}
__device__ __forceinline__ void ldsm4t(uint32_t* r, uint32_t addr) {
    asm volatile("ldmatrix.sync.aligned.m8n8.x4.trans.shared.b16 {%0,%1,%2,%3}, [%4];"
                 : "=r"(r[0]), "=r"(r[1]), "=r"(r[2]), "=r"(r[3]) : "r"(addr));
}
__device__ __forceinline__ void mma16816(float* c, const uint32_t* a,
                                         uint32_t b0, uint32_t b1) {
    asm volatile("mma.sync.aligned.m16n8k16.row.col.f32.f16.f16.f32 "
                 "{%0,%1,%2,%3},{%4,%5,%6,%7},{%8,%9},{%0,%1,%2,%3};"
                 : "+f"(c[0]), "+f"(c[1]), "+f"(c[2]), "+f"(c[3])
                 : "r"(a[0]), "r"(a[1]), "r"(a[2]), "r"(a[3]), "r"(b0), "r"(b1));
}
__device__ __forceinline__ uint32_t h2bits(__half2 h) {
    return *reinterpret_cast<uint32_t*>(&h);
}
__device__ __forceinline__ void cvt_sts(float4 v, char* hi, char* lo, uint32_t off) {
    __half2 h01 = __floats2half2_rn(v.x, v.y);
    __half2 h23 = __floats2half2_rn(v.z, v.w);
    float2 f01 = __half22float2(h01);
    float2 f23 = __half22float2(h23);
    __half2 l01 = __floats2half2_rn(v.x - f01.x, v.y - f01.y);
    __half2 l23 = __floats2half2_rn(v.z - f23.x, v.w - f23.y);
    *(uint2*)(hi + off) = make_uint2(h2bits(h01), h2bits(h23));
    *(uint2*)(lo + off) = make_uint2(h2bits(l01), h2bits(l23));
}

// ---------------- precompute: K -> hi/lo fp16, V -> fp16 ----------------
__global__ void __launch_bounds__(256)
cvt_kernel(const float* __restrict__ K, const float* __restrict__ V)
{
    int idx = blockIdx.x * 256 + threadIdx.x;
    int tsel = idx >> 18;
    int rem  = idx & 262143;
    int d    = rem >> 11;
    int c4   = (rem & 2047) << 2;
    const float* src = tsel ? V : K;
    float4 v = *(const float4*)(src + (size_t)d * N_ + c4);
    __half2 h01 = __floats2half2_rn(v.x, v.y);
    __half2 h23 = __floats2half2_rn(v.z, v.w);
    __half* hi = tsel ? g_Vhi[d] : g_Khi[d];
    *(uint2*)(hi + c4) = make_uint2(h2bits(h01), h2bits(h23));
    if (!tsel) {
        float2 f01 = __half22float2(h01);
        float2 f23 = __half22float2(h23);
        __half2 l01 = __floats2half2_rn(v.x - f01.x, v.y - f01.y);
        __half2 l23 = __floats2half2_rn(v.z - f23.x, v.w - f23.y);
        *(uint2*)(g_Klo[d] + c4) = make_uint2(h2bits(l01), h2bits(l23));
    }
}

__global__ void noop_kernel() {}

__global__ void __launch_bounds__(NTHREADS, 1)
attn_mma(const float* __restrict__ Q)
{
    extern __shared__ __align__(1024) char smem[];
    const uint32_t sb = smem_u32(smem);
    const int tid  = threadIdx.x;
    const int lane = tid & 31;
    const int w    = tid >> 5;
    const int qBase = blockIdx.x * BQ;
    const int kBase = blockIdx.y * KVLEN;
    const int sp    = blockIdx.y;

    const uint32_t mb_full[3] = { sb + SMBAR, sb + SMBAR + 8, sb + SMBAR + 16 };
    const uint32_t mb_free[3] = { sb + SMBAR + 24, sb + SMBAR + 32, sb + SMBAR + 40 };
    const uint32_t mb_stag = sb + SMBAR + 48;

    if (tid == 0) {
        #pragma unroll
        for (int i = 0; i < 3; ++i) {
            mbar_init(mb_full[i], NTHREADS);
            mbar_init(mb_free[i], NTHREADS);
        }
        mbar_init(mb_stag, 128);
    }
    __syncthreads();

    // per-thread cp.async geometry
    int cpd[4], cpk[4];
    uint32_t cpo[4];
    #pragma unroll
    for (int it = 0; it < 4; ++it) {
        int f = tid + it * NTHREADS;           // 0..1023
        cpd[it] = f >> 3;
        cpk[it] = (f & 7) << 3;
        cpo[it] = (uint32_t)(cpd[it] * TSTR + cpk[it]) * 2;
    }

    auto issue_tile = [&](int k0, uint32_t dst) {
        #pragma unroll
        for (int it = 0; it < 4; ++it) {
            const int d = cpd[it], kg = k0 + cpk[it];
            cp16(dst + KH_OFF + cpo[it], g_Khi[d] + kg);
            cp16(dst + KL_OFF + cpo[it], g_Klo[d] + kg);
            cp16(dst + VH_OFF + cpo[it], g_Vhi[d] + kg);
        }
    };

    // ---- stage Q: hi -> SBUF (temp), lo -> SQLO; both log2e-scaled ----
    #pragma unroll
    for (int it = 0; it < 16; ++it) {
        int f = tid + it * NTHREADS;       // 4096 float4s
        int d = f >> 5;
        int qc = (f & 31) << 2;
        float4 v = *(const float4*)(Q + (size_t)d * N_ + qBase + qc);
        v.x *= LOG2E; v.y *= LOG2E; v.z *= LOG2E; v.w *= LOG2E;
        cvt_sts(v, smem + SBUF, smem + SQLO, (uint32_t)(d * QSTR + qc) * 2);
    }
    __syncthreads();

    // per-lane ldmatrix offsets
    const int q0 = w * 16;
    const uint32_t qa_pat =
        (uint32_t)(((((lane >> 4) << 3) + (lane & 7)) * QSTR +
                    q0 + (((lane >> 3) & 1) << 3)) * 2);
    const uint32_t kb_off =
        (uint32_t)(((((lane >> 3) & 1) << 3) + (lane & 7)) * TSTR +
                   (((lane >> 4) << 3))) * 2;
    const uint32_t vb_off =
        (uint32_t)((((lane >> 4) << 3) + (lane & 7)) * TSTR +
                   ((((lane >> 3) & 1) << 3))) * 2;

    // ---- preload Qhi fragments into registers (8 d-steps x 4 regs) ----
    uint32_t qh[8][4];
    {
        const uint32_t qa_hi = sb + SBUF + qa_pat;
        #pragma unroll
        for (int s = 0; s < 8; ++s)
            ldsm4t(qh[s], qa_hi + s * (16 * QSTR * 2));
    }
    __syncthreads();   // staging reads complete before SBUF becomes KV buffers

    // ---- prologue: tiles 0,1 into buffers 0,1 ----
    issue_tile(kBase, sb + SBUF);
    cpasync_mbar_arrive(mb_full[0]);
    issue_tile(kBase + BK, sb + SBUF + BUFB);
    cpasync_mbar_arrive(mb_full[1]);

    const uint32_t qa_lo = sb + SQLO + qa_pat;

    float oacc[16][4];
    #pragma unroll
    for (int i = 0; i < 16; ++i)
        #pragma unroll
        for (int j = 0; j < 4; ++j) oacc[i][j] = 0.0f;
    float m0 = -1e30f, m1 = -1e30f, l0 = 0.0f, l1 = 0.0f;

    // ---- stagger: group B (warps 4-7) starts ~half a tile late ----
    if (w >= 4) mbar_wait(mb_stag, 0);

    for (int t = 0; t < NT; ++t) {
        const int p = t % 3;
        const uint32_t bufK = sb + SBUF + (uint32_t)p * BUFB;
        const uint32_t bufV = bufK + VH_OFF;

        // ---- consume tile t ----
        mbar_wait(mb_full[p], (t / 3) & 1);

        // ---- S = Q^T K: d-outer, Qhi from regs, Qlo ldsm ----
        float acc[8][4];
        #pragma unroll
        for (int i = 0; i < 8; ++i)
            #pragma unroll
            for (int j = 0; j < 4; ++j) acc[i][j] = 0.0f;

        #pragma unroll
        for (int s = 0; s < 8; ++s) {          // d-steps of 16
            uint32_t al[4];
            ldsm4t(al, qa_lo + s * (16 * QSTR * 2));
            #pragma unroll
            for (int c = 0; c < 2; ++c) {      // key chunks of 32
                uint32_t bh0[4], bl0[4], bh1[4], bl1[4];
                uint32_t ka = bufK + kb_off + s * (16 * TSTR * 2) + c * 64;
                ldsm4t(bh0, ka + KH_OFF);
                ldsm4t(bl0, ka + KL_OFF);
                ldsm4t(bh1, ka + KH_OFF + 32);
                ldsm4t(bl1, ka + KL_OFF + 32);
                float* a0 = acc[4 * c];
                float* a1 = acc[4 * c + 1];
                float* a2 = acc[4 * c + 2];
                float* a3 = acc[4 * c + 3];
                mma16816(a0, qh[s], bh0[0], bh0[1]);
                mma16816(a1, qh[s], bh0[2], bh0[3]);
                mma16816(a2, qh[s], bh1[0], bh1[1]);
                mma16816(a3, qh[s], bh1[2], bh1[3]);
                mma16816(a0, qh[s], bl0[0], bl0[1]);
                mma16816(a1, qh[s], bl0[2], bl0[3]);
                mma16816(a2, qh[s], bl1[0], bl1[1]);
                mma16816(a3, qh[s], bl1[2], bl1[3]);
                mma16816(a0, al, bh0[0], bh0[1]);
                mma16816(a1, al, bh0[2], bh0[3]);
                mma16816(a2, al, bh1[0], bh1[1]);
                mma16816(a3, al, bh1[2], bh1[3]);
            }
        }

        // release group B after group A's first S-phase (sets the skew)
        if (t == 0 && w < 4) mbar_arrive(mb_stag);

        // ---- produce tile t+2 (placed after S so the leader never blocks
        //      on the laggard's free-arrive; bounds skew at ~0.45 tile) ----
        if (t + 2 < NT) {
            const int pp = (t + 2) % 3;
            const int m  = (t + 2) / 3;
            if (m >= 1) mbar_wait(mb_free[pp], (m - 1) & 1);
            issue_tile(kBase + (t + 2) * BK, sb + SBUF + (uint32_t)pp * BUFB);
            cpasync_mbar_arrive(mb_full[pp]);
        }

        // ---- per-chunk: softmax + PV ----
        #pragma unroll
        for (int c = 0; c < 2; ++c) {
            float (*ca)[4] = &acc[4 * c];

            float tm0 = -1e30f, tm1 = -1e30f;
            #pragma unroll
            for (int nt = 0; nt < 4; ++nt) {
                tm0 = fmaxf(tm0, fmaxf(ca[nt][0], ca[nt][1]));
                tm1 = fmaxf(tm1, fmaxf(ca[nt][2], ca[nt][3]));
            }
            tm0 = fmaxf(tm0, __shfl_xor_sync(0xffffffffu, tm0, 1));
            tm0 = fmaxf(tm0, __shfl_xor_sync(0xffffffffu, tm0, 2));
            tm1 = fmaxf(tm1, __shfl_xor_sync(0xffffffffu, tm1, 1));
            tm1 = fmaxf(tm1, __shfl_xor_sync(0xffffffffu, tm1, 2));

            bool upd = (tm0 > m0 + THRESH) || (tm1 > m1 + THRESH);
            if (__ballot_sync(0xffffffffu, upd)) {
                float nm0 = fmaxf(m0, tm0), nm1 = fmaxf(m1, tm1);
                float a0 = exp2f(m0 - nm0), a1 = exp2f(m1 - nm1);
                m0 = nm0; m1 = nm1; l0 *= a0; l1 *= a1;
                #pragma unroll
                for (int nt = 0; nt < 16; ++nt) {
                    oacc[nt][0] *= a0; oacc[nt][1] *= a0;
                    oacc[nt][2] *= a1; oacc[nt][3] *= a1;
                }
            }

            #pragma unroll
            for (int sh = 0; sh < 2; ++sh) {
                const int s = 2 * c + sh;      // global k-step
                uint32_t ah[4];
                #pragma unroll
                for (int half = 0; half < 2; ++half) {
                    float* av = ca[2 * sh + half];
                    float p0 = exp2f(av[0] - m0);
                    float p1 = exp2f(av[1] - m0);
                    float p2 = exp2f(av[2] - m1);
                    float p3 = exp2f(av[3] - m1);
                    l0 += p0 + p1; l1 += p2 + p3;
                    ah[2 * half]     = h2bits(__floats2half2_rn(p0, p1));
                    ah[2 * half + 1] = h2bits(__floats2half2_rn(p2, p3));
                }
                #pragma unroll
                for (int np = 0; np < 8; ++np) {   // d-tile pairs (16 dims)
                    uint32_t bh[4];
                    uint32_t va = bufV + vb_off + np * (16 * TSTR * 2) + s * 32;
                    ldsm4(bh, va);
                    mma16816(oacc[2 * np],     ah, bh[0], bh[1]);
                    mma16816(oacc[2 * np + 1], ah, bh[2], bh[3]);
                }
            }
        }

        mbar_arrive(mb_free[p]);   // done reading buffer p
    }

    // ---- epilogue ----
    l0 += __shfl_xor_sync(0xffffffffu, l0, 1);
    l0 += __shfl_xor_sync(0xffffffffu, l0, 2);
    l1 += __shfl_xor_sync(0xffffffffu, l1, 1);
    l1 += __shfl_xor_sync(0xffffffffu, l1, 2);

    const int qr0 = qBase + q0 + (lane >> 2);
    const int qr1 = qr0 + 8;
    if ((lane & 3) == 0) {
        g_m[sp][qr0] = m0; g_m[sp][qr1] = m1;
        g_l[sp][qr0] = l0; g_l[sp][qr1] = l1;
    }
    #pragma unroll
    for (int nt = 0; nt < 16; ++nt) {
        int d = nt * 8 + ((lane & 3) << 1);
        g_Op[sp][d][qr0]     = oacc[nt][0];
        g_Op[sp][d + 1][qr0] = oacc[nt][1];
        g_Op[sp][d][qr1]     = oacc[nt][2];
        g_Op[sp][d + 1][qr1] = oacc[nt][3];
    }
}

__global__ void __launch_bounds__(256)
combine_kernel(float* __restrict__ O)
{
    int idx = blockIdx.x * 256 + threadIdx.x;    // 262144 float4s
    int d  = idx >> 11;
    int q4 = (idx & 2047) << 2;
    float4 o1 = *(const float4*)&g_Op[0][d][q4];
    float4 o2 = *(const float4*)&g_Op[1][d][q4];
    float r[4];
    const float* po1 = &o1.x;
    const float* po2 = &o2.x;
    #pragma unroll
    for (int c = 0; c < 4; ++c) {
        float m1 = g_m[0][q4 + c], m2 = g_m[1][q4 + c];
        float l1 = g_l[0][q4 + c], l2 = g_l[1][q4 + c];
        float M  = fmaxf(m1, m2);
        float w1 = exp2f(m1 - M), w2 = exp2f(m2 - M);
        r[c] = (w1 * po1[c] + w2 * po2[c]) / (w1 * l1 + w2 * l2);
    }
    *(float4*)(O + (size_t)d * N_ + q4) = make_float4(r[0], r[1], r[2], r[3]);
}

} // namespace

extern "C" void kernel_launch(void* const* d_in, const int* in_sizes, int n_in,
                              void* d_out, int out_size) {
    const float* Q = (const float*)d_in[0];
    const float* K = (const float*)d_in[1];
    const float* V = (const float*)d_in[2];
    float* O = (float*)d_out;

    cudaFuncSetAttribute(attn_mma, cudaFuncAttributeMaxDynamicSharedMemorySize,
                         SMEM_BYTES);
    cvt_kernel<<<2048, 256>>>(K, V);          // idx 0
    noop_kernel<<<1, 32>>>();                  // idx 1
    noop_kernel<<<1, 32>>>();                  // idx 2
    dim3 grid(N_ / BQ, SPLIT);
    attn_mma<<<grid, NTHREADS, SMEM_BYTES>>>(Q);   // idx 3 <- ncu
    combine_kernel<<<(D_ * N_ / 4) / 256, 256>>>(O);
}